// round 9
// baseline (speedup 1.0000x reference)
#include <cuda_runtime.h>
#include <cuda_bf16.h>
#include <math.h>

// Problem constants
#define Bz      8192
#define NNETS   30
#define NNODES  20
#define NOUT    10
#define DOUT    16
#define INDIM   784
#define NCOL    600
#define NPAD    640

// Scratch
__device__ unsigned int g_xhl[Bz * INDIM];      // {bf16 hi | bf16 lo<<16} of x
__device__ unsigned int g_whl[NPAD * INDIM];    // transposed W1: [n][k] pairs
__device__ float g_b1p[NPAD];
__device__ float g_h1[Bz * NPAD];

__device__ __forceinline__ unsigned int pack_hl(float x) {
    __nv_bfloat16 h = __float2bfloat16(x);
    float hf = __bfloat162float(h);
    __nv_bfloat16 l = __float2bfloat16(x - hf);
    return (unsigned int)__bfloat16_as_ushort(h) |
           ((unsigned int)__bfloat16_as_ushort(l) << 16);
}

// ---------------------------------------------------------------------------
// P0: convert x to hi/lo bf16 pairs
// ---------------------------------------------------------------------------
__global__ void prep_x_kernel(const float* __restrict__ x) {
    int i = blockIdx.x * blockDim.x + threadIdx.x;
    if (i >= (Bz * INDIM) / 4) return;
    float4 v = ((const float4*)x)[i];
    uint4 o;
    o.x = pack_hl(v.x); o.y = pack_hl(v.y); o.z = pack_hl(v.z); o.w = pack_hl(v.w);
    ((uint4*)g_xhl)[i] = o;
}

// ---------------------------------------------------------------------------
// P1: W1 [30][784][20] -> g_whl [n=640][k=784] pairs (transposed), + bias pad
// ---------------------------------------------------------------------------
__global__ void prep_w_kernel(const float* __restrict__ W1, const float* __restrict__ b1) {
    int idx = blockIdx.x * blockDim.x + threadIdx.x;
    if (idx < NPAD * INDIM) {
        int n = idx / INDIM;
        int k = idx % INDIM;
        float w = 0.f;
        if (n < NCOL) {
            int net = n / NNODES, o = n % NNODES;
            w = W1[net * (INDIM * NNODES) + k * NNODES + o];
        }
        g_whl[n * INDIM + k] = pack_hl(w);
    }
    if (idx < NPAD) g_b1p[idx] = (idx < NCOL) ? b1[idx] : 0.f;
}

// ---------------------------------------------------------------------------
// K1: tensor-core GEMM  h1 = relu(x @ W1 + b1), 3xBF16 split,
// DOUBLE-BUFFERED smem (unchanged from R8).
// ---------------------------------------------------------------------------
#define ASTR 24
#define A_BUF_B (128 * ASTR * 2)
#define B_BUF_B (64 * ASTR * 2)

__device__ __forceinline__ void ldsm4(unsigned& r0, unsigned& r1, unsigned& r2, unsigned& r3,
                                      unsigned addr) {
    asm volatile("ldmatrix.sync.aligned.m8n8.x4.shared.b16 {%0,%1,%2,%3}, [%4];\n"
                 : "=r"(r0), "=r"(r1), "=r"(r2), "=r"(r3) : "r"(addr));
}
__device__ __forceinline__ void mma16816(float* d, const unsigned* a, const unsigned* b) {
    asm volatile(
        "mma.sync.aligned.m16n8k16.row.col.f32.bf16.bf16.f32 "
        "{%0,%1,%2,%3}, {%4,%5,%6,%7}, {%8,%9}, {%0,%1,%2,%3};\n"
        : "+f"(d[0]), "+f"(d[1]), "+f"(d[2]), "+f"(d[3])
        : "r"(a[0]), "r"(a[1]), "r"(a[2]), "r"(a[3]), "r"(b[0]), "r"(b[1]));
}

__global__ __launch_bounds__(256) void gemm1_tc_kernel() {
    __shared__ __align__(16) unsigned short Ah[2][128 * ASTR];
    __shared__ __align__(16) unsigned short Al[2][128 * ASTR];
    __shared__ __align__(16) unsigned short Bh[2][64 * ASTR];
    __shared__ __align__(16) unsigned short Bl[2][64 * ASTR];

    const int tid  = threadIdx.x;
    const int bm   = blockIdx.x & 63;
    const int bn   = blockIdx.x >> 6;
    const int warp = tid >> 5;
    const int lane = tid & 31;
    const int wm   = warp >> 1;
    const int wn   = warp & 1;

    const int sr = tid >> 2;
    const int sc = tid & 3;
    const uint4* xg = (const uint4*)g_xhl;
    const uint4* wg = (const uint4*)g_whl;
    const size_t arow0 = (size_t)(bm * 128 + sr) * INDIM;
    const size_t arow1 = (size_t)(bm * 128 + 64 + sr) * INDIM;
    const size_t brow  = (size_t)(bn * 64 + sr) * INDIM;

    float acc[2][4][4];
    #pragma unroll
    for (int i = 0; i < 2; i++)
        #pragma unroll
        for (int j = 0; j < 4; j++)
            #pragma unroll
            for (int q = 0; q < 4; q++) acc[i][j][q] = 0.f;

    const int mi = lane >> 3, lr = lane & 7;
    const int a_row = lr + ((mi & 1) << 3);
    const int a_cb  = (mi >> 1) << 4;
    const int b_row = lr + ((mi >> 1) << 3);
    const int b_cb  = (mi & 1) << 4;

    unsigned aAddrH0[2], aAddrL0[2], bAddrH0[2], bAddrL0[2];
    #pragma unroll
    for (int mt = 0; mt < 2; mt++) {
        int r = wm * 32 + mt * 16 + a_row;
        aAddrH0[mt] = (unsigned)__cvta_generic_to_shared(&Ah[0][r * ASTR]) + a_cb;
        aAddrL0[mt] = (unsigned)__cvta_generic_to_shared(&Al[0][r * ASTR]) + a_cb;
    }
    #pragma unroll
    for (int p = 0; p < 2; p++) {
        int r = wn * 32 + p * 16 + b_row;
        bAddrH0[p] = (unsigned)__cvta_generic_to_shared(&Bh[0][r * ASTR]) + b_cb;
        bAddrL0[p] = (unsigned)__cvta_generic_to_shared(&Bl[0][r * ASTR]) + b_cb;
    }

    uint4 a0r = xg[arow0 / 4 + sc];
    uint4 a1r = xg[arow1 / 4 + sc];
    uint4 b0r = wg[brow  / 4 + sc];

    {
        unsigned short* AhP = Ah[0]; unsigned short* AlP = Al[0];
        unsigned short* BhP = Bh[0]; unsigned short* BlP = Bl[0];
        unsigned hi0 = (a0r.x & 0xffffu) | (a0r.y << 16);
        unsigned hi1 = (a0r.z & 0xffffu) | (a0r.w << 16);
        unsigned lo0 = (a0r.x >> 16) | (a0r.y & 0xffff0000u);
        unsigned lo1 = (a0r.z >> 16) | (a0r.w & 0xffff0000u);
        *(uint2*)&AhP[sr * ASTR + sc * 4] = make_uint2(hi0, hi1);
        *(uint2*)&AlP[sr * ASTR + sc * 4] = make_uint2(lo0, lo1);
        hi0 = (a1r.x & 0xffffu) | (a1r.y << 16);
        hi1 = (a1r.z & 0xffffu) | (a1r.w << 16);
        lo0 = (a1r.x >> 16) | (a1r.y & 0xffff0000u);
        lo1 = (a1r.z >> 16) | (a1r.w & 0xffff0000u);
        *(uint2*)&AhP[(64 + sr) * ASTR + sc * 4] = make_uint2(hi0, hi1);
        *(uint2*)&AlP[(64 + sr) * ASTR + sc * 4] = make_uint2(lo0, lo1);
        hi0 = (b0r.x & 0xffffu) | (b0r.y << 16);
        hi1 = (b0r.z & 0xffffu) | (b0r.w << 16);
        lo0 = (b0r.x >> 16) | (b0r.y & 0xffff0000u);
        lo1 = (b0r.z >> 16) | (b0r.w & 0xffff0000u);
        *(uint2*)&BhP[sr * ASTR + sc * 4] = make_uint2(hi0, hi1);
        *(uint2*)&BlP[sr * ASTR + sc * 4] = make_uint2(lo0, lo1);
    }
    __syncthreads();

    for (int kt = 0; kt < 49; kt++) {
        const int cur = kt & 1;
        const unsigned aOff = cur ? A_BUF_B : 0;
        const unsigned bOff = cur ? B_BUF_B : 0;

        if (kt < 48) {
            int kb = (kt + 1) * 16;
            a0r = xg[(arow0 + kb) / 4 + sc];
            a1r = xg[(arow1 + kb) / 4 + sc];
            b0r = wg[(brow  + kb) / 4 + sc];
        }

        unsigned ah[2][4], al[2][4], bh[4][2], bl[4][2];
        #pragma unroll
        for (int mt = 0; mt < 2; mt++) {
            ldsm4(ah[mt][0], ah[mt][1], ah[mt][2], ah[mt][3], aAddrH0[mt] + aOff);
            ldsm4(al[mt][0], al[mt][1], al[mt][2], al[mt][3], aAddrL0[mt] + aOff);
        }
        #pragma unroll
        for (int p = 0; p < 2; p++) {
            ldsm4(bh[2*p][0], bh[2*p][1], bh[2*p+1][0], bh[2*p+1][1], bAddrH0[p] + bOff);
            ldsm4(bl[2*p][0], bl[2*p][1], bl[2*p+1][0], bl[2*p+1][1], bAddrL0[p] + bOff);
        }

        #pragma unroll
        for (int mt = 0; mt < 2; mt++)
            #pragma unroll
            for (int nt = 0; nt < 4; nt++) {
                mma16816(acc[mt][nt], ah[mt], bh[nt]);
                mma16816(acc[mt][nt], ah[mt], bl[nt]);
                mma16816(acc[mt][nt], al[mt], bh[nt]);
            }

        if (kt < 48) {
            const int nxt = (kt + 1) & 1;
            unsigned short* AhP = Ah[nxt]; unsigned short* AlP = Al[nxt];
            unsigned short* BhP = Bh[nxt]; unsigned short* BlP = Bl[nxt];
            unsigned hi0 = (a0r.x & 0xffffu) | (a0r.y << 16);
            unsigned hi1 = (a0r.z & 0xffffu) | (a0r.w << 16);
            unsigned lo0 = (a0r.x >> 16) | (a0r.y & 0xffff0000u);
            unsigned lo1 = (a0r.z >> 16) | (a0r.w & 0xffff0000u);
            *(uint2*)&AhP[sr * ASTR + sc * 4] = make_uint2(hi0, hi1);
            *(uint2*)&AlP[sr * ASTR + sc * 4] = make_uint2(lo0, lo1);
            hi0 = (a1r.x & 0xffffu) | (a1r.y << 16);
            hi1 = (a1r.z & 0xffffu) | (a1r.w << 16);
            lo0 = (a1r.x >> 16) | (a1r.y & 0xffff0000u);
            lo1 = (a1r.z >> 16) | (a1r.w & 0xffff0000u);
            *(uint2*)&AhP[(64 + sr) * ASTR + sc * 4] = make_uint2(hi0, hi1);
            *(uint2*)&AlP[(64 + sr) * ASTR + sc * 4] = make_uint2(lo0, lo1);
            hi0 = (b0r.x & 0xffffu) | (b0r.y << 16);
            hi1 = (b0r.z & 0xffffu) | (b0r.w << 16);
            lo0 = (b0r.x >> 16) | (b0r.y & 0xffff0000u);
            lo1 = (b0r.z >> 16) | (b0r.w & 0xffff0000u);
            *(uint2*)&BhP[sr * ASTR + sc * 4] = make_uint2(hi0, hi1);
            *(uint2*)&BlP[sr * ASTR + sc * 4] = make_uint2(lo0, lo1);
        }
        __syncthreads();
    }

    const int g = lane >> 2, t = lane & 3;
    #pragma unroll
    for (int mt = 0; mt < 2; mt++) {
        #pragma unroll
        for (int nt = 0; nt < 4; nt++) {
            int col = bn * 64 + wn * 32 + nt * 8 + t * 2;
            float2 bias = *(const float2*)&g_b1p[col];
            int row0 = bm * 128 + wm * 32 + mt * 16 + g;
            float2 v0, v1;
            v0.x = fmaxf(acc[mt][nt][0] + bias.x, 0.f);
            v0.y = fmaxf(acc[mt][nt][1] + bias.y, 0.f);
            v1.x = fmaxf(acc[mt][nt][2] + bias.x, 0.f);
            v1.y = fmaxf(acc[mt][nt][3] + bias.y, 0.f);
            *(float2*)&g_h1[(size_t)row0 * NPAD + col]       = v0;
            *(float2*)&g_h1[(size_t)(row0 + 8) * NPAD + col] = v1;
        }
    }
}

// ---------------------------------------------------------------------------
// K3 v9: wavefront-optimized fused layer2 + priors + routing.
//  - h1 rows prestaged into smem (coalesced), stage1b reads smem
//  - stage 2 warp map (n slowest) -> u reads are warp broadcasts
//  - phase d 4-lane cooperative (contiguous 64B pri reads + shfl reduce)
// ---------------------------------------------------------------------------
#define RMB     8
#define PRI_F   (RMB * 300 * 20)     // 48000
#define REG2_F  (RMB * 600)          // 4800
#define PB_F    (RMB * 300)          // 2400
#define VV_F    (RMB * 160)          // 1280
#define RT_SMEM_BYTES ((PRI_F + REG2_F + PB_F + VV_F) * 4)   // 225920
#define RT_THREADS 768

__global__ __launch_bounds__(RT_THREADS, 1) void routing_kernel(const float* __restrict__ W2,
                                                                const float* __restrict__ b2,
                                                                const float* __restrict__ rw,
                                                                float* __restrict__ out) {
    extern __shared__ float sm[];
    float* pri  = sm;                 // [mb][pair][20]
    float* reg2 = sm + PRI_F;
    float* pb   = reg2 + REG2_F;      // [mb][300]
    float* vv   = pb + PB_F;          // [mb][160]
    float* us   = reg2;               // [mb][600]   (live: stage1..priors)
    float* lg   = reg2;               // [mb][300]   (live: it0 phase d..end)
    float* W2s  = pri;                // [30][400]   (live: stage1 only)
    float* b2s  = pri + 12000;        // [600]
    float* hs   = pri + 16000;        // [mb][600]   (live: stage1 only)

    const int tid = threadIdx.x;
    const int b0  = blockIdx.x * RMB;

    // ---- stage 1a: W2 + b2 + h1 rows into smem (coalesced) ----
    for (int i = tid; i < 3150 + 1200; i += RT_THREADS) {
        if (i < 3000) {
            ((float4*)W2s)[i] = ((const float4*)W2)[i];
        } else if (i < 3150) {
            ((float4*)b2s)[i - 3000] = ((const float4*)b2)[i - 3000];
        } else {
            int j  = i - 3150;          // 0..1199
            int mb = j / 150, q = j % 150;
            ((float4*)(hs + mb * 600))[q] =
                *(const float4*)&g_h1[(size_t)(b0 + mb) * NPAD + q * 4];
        }
    }
    __syncthreads();

    // ---- stage 1b: u = squash(relu(h1 @ W2 + b2)) ----
    if (tid < 240) {
        const int n  = tid >> 3;
        const int mb = tid & 7;

        float4 h4[5];
        const float4* hp = (const float4*)(hs + mb * 600 + n * NNODES);
        #pragma unroll
        for (int q = 0; q < 5; q++) h4[q] = hp[q];
        const float* h = (const float*)h4;

        float4 a4[5];
        const float4* bp = (const float4*)(b2s + n * NNODES);
        #pragma unroll
        for (int q = 0; q < 5; q++) a4[q] = bp[q];
        float* acc = (float*)a4;

        const float4* w4 = (const float4*)(W2s + n * 400);
        #pragma unroll
        for (int d = 0; d < NNODES; d++) {
            float hd = h[d];
            #pragma unroll
            for (int q = 0; q < 5; q++) {
                float4 w = w4[d * 5 + q];
                acc[q * 4 + 0] = fmaf(hd, w.x, acc[q * 4 + 0]);
                acc[q * 4 + 1] = fmaf(hd, w.y, acc[q * 4 + 1]);
                acc[q * 4 + 2] = fmaf(hd, w.z, acc[q * 4 + 2]);
                acc[q * 4 + 3] = fmaf(hd, w.w, acc[q * 4 + 3]);
            }
        }
        float sq = 0.f;
        #pragma unroll
        for (int e = 0; e < NNODES; e++) {
            acc[e] = fmaxf(acc[e], 0.f);
            sq = fmaf(acc[e], acc[e], sq);
        }
        float f = sqrtf(sq) / (1.f + sq);
        float* up = us + mb * 600 + n * NNODES;
        #pragma unroll
        for (int q = 0; q < 5; q++) {
            float4 o;
            o.x = acc[q * 4 + 0] * f;
            o.y = acc[q * 4 + 1] * f;
            o.z = acc[q * 4 + 2] * f;
            o.w = acc[q * 4 + 3] * f;
            *(float4*)&up[q * 4] = o;
        }
    }
    __syncthreads();   // u ready; W2s/hs (pri) dead

    // ---- stage 2: priors. warp map: n slowest -> u reads broadcast ----
    #pragma unroll
    for (int g = 0; g < 2; g++) {
        int t = tid + RT_THREADS * g;
        if (t < 1200) {
            const int n  = t / 40;            // same n across a warp (<=2)
            const int r  = t % 40;
            const int o  = r >> 2;
            const int kq = r & 3;
            const int pair = o * NNETS + n;
            const float* rwp = rw + (size_t)pair * 320 + kq * 4;
            const float* ub  = us + n * 20;

            float acc[RMB][4];
            #pragma unroll
            for (int mb = 0; mb < RMB; mb++) {
                acc[mb][0] = 0.f; acc[mb][1] = 0.f; acc[mb][2] = 0.f; acc[mb][3] = 0.f;
            }
            #pragma unroll
            for (int dq = 0; dq < 5; dq++) {
                float4 w0 = *(const float4*)&rwp[(dq * 4 + 0) * 16];
                float4 w1 = *(const float4*)&rwp[(dq * 4 + 1) * 16];
                float4 w2 = *(const float4*)&rwp[(dq * 4 + 2) * 16];
                float4 w3 = *(const float4*)&rwp[(dq * 4 + 3) * 16];
                #pragma unroll
                for (int mb = 0; mb < RMB; mb++) {
                    float4 uq = *(const float4*)&ub[mb * 600 + dq * 4];
                    acc[mb][0] = fmaf(w0.x, uq.x, acc[mb][0]);
                    acc[mb][1] = fmaf(w0.y, uq.x, acc[mb][1]);
                    acc[mb][2] = fmaf(w0.z, uq.x, acc[mb][2]);
                    acc[mb][3] = fmaf(w0.w, uq.x, acc[mb][3]);
                    acc[mb][0] = fmaf(w1.x, uq.y, acc[mb][0]);
                    acc[mb][1] = fmaf(w1.y, uq.y, acc[mb][1]);
                    acc[mb][2] = fmaf(w1.z, uq.y, acc[mb][2]);
                    acc[mb][3] = fmaf(w1.w, uq.y, acc[mb][3]);
                    acc[mb][0] = fmaf(w2.x, uq.z, acc[mb][0]);
                    acc[mb][1] = fmaf(w2.y, uq.z, acc[mb][1]);
                    acc[mb][2] = fmaf(w2.z, uq.z, acc[mb][2]);
                    acc[mb][3] = fmaf(w2.w, uq.z, acc[mb][3]);
                    acc[mb][0] = fmaf(w3.x, uq.w, acc[mb][0]);
                    acc[mb][1] = fmaf(w3.y, uq.w, acc[mb][1]);
                    acc[mb][2] = fmaf(w3.z, uq.w, acc[mb][2]);
                    acc[mb][3] = fmaf(w3.w, uq.w, acc[mb][3]);
                }
            }
            #pragma unroll
            for (int mb = 0; mb < RMB; mb++)
                *(float4*)&pri[mb * 6000 + pair * 20 + kq * 4] =
                    make_float4(acc[mb][0], acc[mb][1], acc[mb][2], acc[mb][3]);
        }
    }
    __syncthreads();   // pri ready; us dead -> lg region free

    // ---- stage 3: routing iterations ----
    for (int it = 0; it < 3; it++) {
        if (it > 0) {
            if (tid < RMB * NNETS) {
                int mb = tid / NNETS, n = tid % NNETS;
                const float* L = lg + mb * 300 + n;
                float lo[NOUT];
                float m = -1e30f;
                #pragma unroll
                for (int o = 0; o < NOUT; o++) { lo[o] = L[o * 30]; m = fmaxf(m, lo[o]); }
                float e[NOUT], ss = 0.f;
                #pragma unroll
                for (int o = 0; o < NOUT; o++) { e[o] = __expf(lo[o] - m); ss += e[o]; }
                float inv = 1.f / ss;
                float* P = pb + mb * 300 + n;
                #pragma unroll
                for (int o = 0; o < NOUT; o++) P[o * 30] = e[o] * inv;
            }
            __syncthreads();
        }

        // phase b/c: 640 threads: (mb, o, k-pair). squash via 3 shfls.
        if (tid < 640) {
            const int mb  = tid / 80;
            const int r   = tid % 80;
            const int o   = r >> 3;
            const int kh8 = r & 7;
            const int k0  = kh8 * 2;
            const float* PR = pri + mb * 6000 + o * 600 + k0;
            const float* P  = pb  + mb * 300  + o * 30;

            float s0 = 0.f, s1 = 0.f;
            #pragma unroll 6
            for (int n = 0; n < NNETS; n++) {
                float p = (it == 0) ? 0.1f : P[n];
                float2 q = *(const float2*)&PR[n * 20];
                s0 = fmaf(p, q.x, s0);
                s1 = fmaf(p, q.y, s1);
            }
            float sq = fmaf(s0, s0, s1 * s1);
            sq += __shfl_xor_sync(0xffffffffu, sq, 1);
            sq += __shfl_xor_sync(0xffffffffu, sq, 2);
            sq += __shfl_xor_sync(0xffffffffu, sq, 4);
            float f = sqrtf(sq) / (1.f + sq);
            float v0 = s0 * f, v1 = s1 * f;

            if (it < 2) {
                *(float2*)&vv[mb * 160 + o * 16 + k0] = make_float2(v0, v1);
            } else {
                *(float2*)&out[(size_t)(b0 + mb) * 160 + o * 16 + k0] =
                    make_float2(v0, v1);
            }
        }

        if (it < 2) {
            __syncthreads();
            // phase d: 9600 lane-tasks (mb, pair, kq); 4-lane cooperative.
            #pragma unroll
            for (int pass = 0; pass < 13; pass++) {
                int j = tid + pass * RT_THREADS;
                if (j < 9600) {
                    int kq = j & 3;
                    int rr = j >> 2;            // 0..2399 = mb*300 + r
                    int mb = rr / 300;
                    int r  = rr % 300;
                    int o  = r / 30;
                    float4 a = *(const float4*)&pri[mb * 6000 + r * 20 + kq * 4];
                    float4 b = *(const float4*)&vv[mb * 160 + o * 16 + kq * 4];
                    float dl = a.x * b.x;
                    dl = fmaf(a.y, b.y, dl);
                    dl = fmaf(a.z, b.z, dl);
                    dl = fmaf(a.w, b.w, dl);
                    dl += __shfl_xor_sync(0xffffffffu, dl, 1);
                    dl += __shfl_xor_sync(0xffffffffu, dl, 2);
                    if (kq == 0) {
                        if (it == 0) lg[rr] = dl;
                        else         lg[rr] += dl;
                    }
                }
            }
            __syncthreads();
        }
    }
}

// ---------------------------------------------------------------------------
extern "C" void kernel_launch(void* const* d_in, const int* in_sizes, int n_in,
                              void* d_out, int out_size) {
    const float* x  = (const float*)d_in[0];
    const float* W1 = (const float*)d_in[1];
    const float* b1 = (const float*)d_in[2];
    const float* W2 = (const float*)d_in[3];
    const float* b2 = (const float*)d_in[4];
    const float* rw = (const float*)d_in[5];
    float* out = (float*)d_out;

    (void)in_sizes; (void)n_in; (void)out_size;

    prep_x_kernel<<<(Bz * INDIM / 4 + 255) / 256, 256>>>(x);
    prep_w_kernel<<<(NPAD * INDIM + 255) / 256, 256>>>(W1, b1);
    gemm1_tc_kernel<<<64 * 10, 256>>>();

    cudaFuncSetAttribute(routing_kernel,
                         cudaFuncAttributeMaxDynamicSharedMemorySize, RT_SMEM_BYTES);
    routing_kernel<<<Bz / RMB, RT_THREADS, RT_SMEM_BYTES>>>(W2, b2, rw, out);
}